// round 1
// baseline (speedup 1.0000x reference)
#include <cuda_runtime.h>
#include <math.h>

#define NBATCH 8
#define LSEQ   4096
#define SSEQ   4096
#define CDIM   256
#define HHEADS 8
#define DHEAD  32
#define MROWS  (NBATCH * LSEQ)   // 32768

// ---------------- scratch (static device globals; no allocs) ----------------
__device__ float g_Q   [MROWS * CDIM];      // elu(query)+1
__device__ float g_Qpos[MROWS * CDIM];      // rotary(query)
__device__ float g_Kpos[MROWS * CDIM];      // rotary(key)
__device__ float g_Vrot[MROWS * CDIM];      // rotary(value)
__device__ float g_Qr  [MROWS * CDIM];      // queried (pre-Wm)
__device__ float g_msg [MROWS * CDIM];      // message buffer (post-Wm / post-LN1)
__device__ float g_msg2[MROWS * CDIM];      // message buffer (post-W2)
__device__ float g_h   [MROWS * 2 * CDIM];  // hidden (post-W1/relu)
__device__ float g_Ksum[NBATCH * CDIM];                   // sum_s elu(key)+1
__device__ float g_KV  [NBATCH * HHEADS * DHEAD * DHEAD]; // Kpos^T @ Vrot

enum { MODE_Q = 0, MODE_K = 1, MODE_V = 2, MODE_M = 3, MODE_H = 4, MODE_O = 5 };

// ---------------- zero accumulators ----------------
__global__ void zero_kernel() {
    int i = blockIdx.x * blockDim.x + threadIdx.x;
    if (i < NBATCH * HHEADS * DHEAD * DHEAD) g_KV[i] = 0.f;
    if (i < NBATCH * CDIM) g_Ksum[i] = 0.f;
}

// ---------------- generic 128x128x8 SGEMM with fused epilogues ----------------
// MODE_Q: out g_Q (elu+1), g_Qpos (rotary)           A = x,       B = Wq, pe = x_pe
// MODE_K: out g_Kpos (rotary), g_Ksum (atomic sum)   A = source,  B = Wk, pe = source_pe
// MODE_V: out g_Vrot (rotary)                        A = source,  B = Wv, pe = source_pe
// MODE_M: out g_msg                                  A = g_Qr,    B = Wm
// MODE_H: out g_h (relu), A = concat(x, g_msg)       A = x,       B = W1
// MODE_O: out g_msg2                                 A = g_h,     B = W2
template <int MODE>
__global__ __launch_bounds__(256, 2) void gemm_k(
    const float* __restrict__ A, const float* __restrict__ B,
    const float* __restrict__ pe, int K, int Ncols)
{
    __shared__ float As[8][128];
    __shared__ float Bs[8][128];
    __shared__ float sCsum[128];

    const int tid     = threadIdx.x;
    const int rowBase = blockIdx.y * 128;
    const int colBase = blockIdx.x * 128;
    const int tx = tid & 15, ty = tid >> 4;

    const float* Aeff = (MODE == MODE_M) ? g_Qr : (MODE == MODE_O) ? g_h : A;

    float acc[8][8];
#pragma unroll
    for (int i = 0; i < 8; i++)
#pragma unroll
        for (int j = 0; j < 8; j++) acc[i][j] = 0.f;

    const int arow = rowBase + (tid >> 1);
    const int ak4  = (tid & 1) * 4;
    const int bk   = tid >> 5;
    const int bn   = (tid & 31) * 4;

    for (int k0 = 0; k0 < K; k0 += 8) {
        float4 av;
        if (MODE == MODE_H) {
            int kg = k0 + ak4;
            const float* src = (kg < CDIM)
                ? (A     + (size_t)arow * CDIM + kg)
                : (g_msg + (size_t)arow * CDIM + (kg - CDIM));
            av = *(const float4*)src;
        } else {
            av = *(const float4*)(Aeff + (size_t)arow * K + k0 + ak4);
        }
        As[ak4 + 0][tid >> 1] = av.x;
        As[ak4 + 1][tid >> 1] = av.y;
        As[ak4 + 2][tid >> 1] = av.z;
        As[ak4 + 3][tid >> 1] = av.w;
        *(float4*)&Bs[bk][bn] =
            *(const float4*)(B + (size_t)(k0 + bk) * Ncols + colBase + bn);
        __syncthreads();
#pragma unroll
        for (int kk = 0; kk < 8; kk++) {
            float a[8], b[8];
            *(float4*)&a[0] = *(const float4*)&As[kk][ty * 8];
            *(float4*)&a[4] = *(const float4*)&As[kk][ty * 8 + 4];
            *(float4*)&b[0] = *(const float4*)&Bs[kk][tx * 8];
            *(float4*)&b[4] = *(const float4*)&Bs[kk][tx * 8 + 4];
#pragma unroll
            for (int i = 0; i < 8; i++)
#pragma unroll
                for (int j = 0; j < 8; j++) acc[i][j] += a[i] * b[j];
        }
        __syncthreads();
    }

    // ----- epilogues -----
    if (MODE == MODE_M || MODE == MODE_O || MODE == MODE_H) {
        float* out = (MODE == MODE_M) ? g_msg : (MODE == MODE_O) ? g_msg2 : g_h;
#pragma unroll
        for (int i = 0; i < 8; i++) {
            int r = rowBase + ty * 8 + i;
            float v[8];
#pragma unroll
            for (int j = 0; j < 8; j++) {
                v[j] = acc[i][j];
                if (MODE == MODE_H) v[j] = fmaxf(v[j], 0.f);
            }
            float* dst = out + (size_t)r * Ncols + colBase + tx * 8;
            *(float4*)&dst[0] = make_float4(v[0], v[1], v[2], v[3]);
            *(float4*)&dst[4] = make_float4(v[4], v[5], v[6], v[7]);
        }
    } else {
        // Q/K/V epilogue: rotary (+ feature map for Q/K, + block Ksum for K)
        float csum[8];
#pragma unroll
        for (int j = 0; j < 8; j++) csum[j] = 0.f;
        if (MODE == MODE_K) {
            if (tid < 128) sCsum[tid] = 0.f;
            __syncthreads();
        }
#pragma unroll
        for (int i = 0; i < 8; i++) {
            int r = rowBase + ty * 8 + i;
            const float* per = pe + ((size_t)r * CDIM + colBase + tx * 8) * 2;
            float rot[8];
#pragma unroll
            for (int jp = 0; jp < 4; jp++) {
                float qe = acc[i][2 * jp], qo = acc[i][2 * jp + 1];
                float ce = per[4 * jp + 0], se = per[4 * jp + 1];
                float co = per[4 * jp + 2], so = per[4 * jp + 3];
                rot[2 * jp]     = qe * ce - qo * se;
                rot[2 * jp + 1] = qo * co + qe * so;
            }
            float* outrot = (MODE == MODE_Q) ? g_Qpos
                           : (MODE == MODE_K) ? g_Kpos : g_Vrot;
            float* dst = outrot + (size_t)r * CDIM + colBase + tx * 8;
            *(float4*)&dst[0] = make_float4(rot[0], rot[1], rot[2], rot[3]);
            *(float4*)&dst[4] = make_float4(rot[4], rot[5], rot[6], rot[7]);

            if (MODE == MODE_Q || MODE == MODE_K) {
                float feat[8];
#pragma unroll
                for (int j = 0; j < 8; j++) {
                    float q = acc[i][j];
                    feat[j] = (q > 0.f) ? (q + 1.f) : expf(q);  // elu(q)+1
                }
                if (MODE == MODE_Q) {
                    float* fd = g_Q + (size_t)r * CDIM + colBase + tx * 8;
                    *(float4*)&fd[0] = make_float4(feat[0], feat[1], feat[2], feat[3]);
                    *(float4*)&fd[4] = make_float4(feat[4], feat[5], feat[6], feat[7]);
                } else {
#pragma unroll
                    for (int j = 0; j < 8; j++) csum[j] += feat[j];
                }
            }
        }
        if (MODE == MODE_K) {
#pragma unroll
            for (int j = 0; j < 8; j++) atomicAdd(&sCsum[tx * 8 + j], csum[j]);
            __syncthreads();
            if (tid < 128) {
                int n = rowBase / SSEQ;
                atomicAdd(&g_Ksum[n * CDIM + colBase + tid], sCsum[tid]);
            }
        }
    }
}

// ---------------- KV = sum_s Kpos[s,h,:] (x) Vrot[s,h,:]  (per n,h) --------
__global__ __launch_bounds__(256) void kv_kernel() {
    const int nh = blockIdx.x;
    const int n = nh / HHEADS, h = nh % HHEADS;
    const int s0 = blockIdx.y * (SSEQ / 8);
    __shared__ float sK[16][DHEAD];
    __shared__ float sV[16][DHEAD];
    const int t  = threadIdx.x;
    const int d  = t >> 3;          // 0..31
    const int vb = (t & 7) * 4;     // 0,4,...,28
    float acc0 = 0.f, acc1 = 0.f, acc2 = 0.f, acc3 = 0.f;

    for (int sc = 0; sc < SSEQ / 8; sc += 16) {
#pragma unroll
        for (int rep = 0; rep < 2; rep++) {
            int idx = t + rep * 256;
            int sr = idx >> 5, c = idx & 31;
            int off = (n * SSEQ + s0 + sc + sr) * CDIM + h * DHEAD + c;
            sK[sr][c] = g_Kpos[off];
            sV[sr][c] = g_Vrot[off];
        }
        __syncthreads();
#pragma unroll
        for (int sr = 0; sr < 16; sr++) {
            float kd = sK[sr][d];
            float4 v = *(const float4*)&sV[sr][vb];
            acc0 += kd * v.x; acc1 += kd * v.y;
            acc2 += kd * v.z; acc3 += kd * v.w;
        }
        __syncthreads();
    }
    float* dst = &g_KV[((n * HHEADS + h) * DHEAD + d) * DHEAD + vb];
    atomicAdd(dst + 0, acc0); atomicAdd(dst + 1, acc1);
    atomicAdd(dst + 2, acc2); atomicAdd(dst + 3, acc3);
}

// ------- queried = (Qpos . KV) / (Q . Ksum + eps) ; (the /S * S cancels) ----
__global__ __launch_bounds__(256) void queried_kernel() {
    const int blk = blockIdx.x;
    const int n  = blk / (LSEQ / 64);
    const int l0 = (blk % (LSEQ / 64)) * 64;
    __shared__ float sKV[HHEADS * DHEAD * DHEAD];  // 32 KB
    __shared__ float sKs[CDIM];
    __shared__ float sQ[CDIM];
    __shared__ float sQp[CDIM];
    const int t = threadIdx.x;
    for (int i = t; i < HHEADS * DHEAD * DHEAD; i += 256)
        sKV[i] = g_KV[n * HHEADS * DHEAD * DHEAD + i];
    sKs[t] = g_Ksum[n * CDIM + t];
    __syncthreads();

    const int h = t >> 5, lane = t & 31;
    const float* kvh = &sKV[h * DHEAD * DHEAD];
    for (int l = l0; l < l0 + 64; l++) {
        int base = (n * LSEQ + l) * CDIM;
        sQ[t]  = g_Q[base + t];
        sQp[t] = g_Qpos[base + t];
        __syncthreads();
        float p = sQ[h * DHEAD + lane] * sKs[h * DHEAD + lane];
#pragma unroll
        for (int o = 16; o; o >>= 1) p += __shfl_xor_sync(0xffffffffu, p, o);
        float z = 1.0f / (p + 1e-6f);
        float s1 = 0.f;
#pragma unroll
        for (int dd = 0; dd < DHEAD; dd++)
            s1 += sQp[h * DHEAD + dd] * kvh[dd * DHEAD + lane];
        g_Qr[base + t] = s1 * z;
        __syncthreads();
    }
}

// ---------------- LayerNorm helpers ----------------
__device__ __forceinline__ float blk_sum256(float v, float* red) {
#pragma unroll
    for (int o = 16; o; o >>= 1) v += __shfl_xor_sync(0xffffffffu, v, o);
    if ((threadIdx.x & 31) == 0) red[threadIdx.x >> 5] = v;
    __syncthreads();
    float s = red[0] + red[1] + red[2] + red[3] +
              red[4] + red[5] + red[6] + red[7];
    __syncthreads();
    return s;
}

__global__ __launch_bounds__(256) void ln1_kernel(
    const float* __restrict__ g, const float* __restrict__ b)
{
    __shared__ float red[8];
    const int r = blockIdx.x, t = threadIdx.x;
    float v = g_msg[(size_t)r * CDIM + t];
    float m = blk_sum256(v, red) * (1.f / CDIM);
    float d = v - m;
    float var = blk_sum256(d * d, red) * (1.f / CDIM);
    g_msg[(size_t)r * CDIM + t] = d * rsqrtf(var + 1e-5f) * g[t] + b[t];
}

__global__ __launch_bounds__(256) void ln2_res_kernel(
    const float* __restrict__ x, const float* __restrict__ g,
    const float* __restrict__ b, float* __restrict__ out)
{
    __shared__ float red[8];
    const int r = blockIdx.x, t = threadIdx.x;
    float v = g_msg2[(size_t)r * CDIM + t];
    float m = blk_sum256(v, red) * (1.f / CDIM);
    float d = v - m;
    float var = blk_sum256(d * d, red) * (1.f / CDIM);
    out[(size_t)r * CDIM + t] =
        x[(size_t)r * CDIM + t] + d * rsqrtf(var + 1e-5f) * g[t] + b[t];
}

// ---------------- launch ----------------
extern "C" void kernel_launch(void* const* d_in, const int* in_sizes, int n_in,
                              void* d_out, int out_size)
{
    const float* x      = (const float*)d_in[0];
    const float* source = (const float*)d_in[1];
    const float* x_pe   = (const float*)d_in[2];
    const float* s_pe   = (const float*)d_in[3];
    const float* Wq     = (const float*)d_in[4];
    const float* Wk     = (const float*)d_in[5];
    const float* Wv     = (const float*)d_in[6];
    const float* Wm     = (const float*)d_in[7];
    const float* W1     = (const float*)d_in[8];
    const float* W2     = (const float*)d_in[9];
    const float* ln1_g  = (const float*)d_in[10];
    const float* ln1_b  = (const float*)d_in[11];
    const float* ln2_g  = (const float*)d_in[12];
    const float* ln2_b  = (const float*)d_in[13];
    float* out = (float*)d_out;

    zero_kernel<<<256, 256>>>();

    dim3 gP(CDIM / 128, MROWS / 128);           // 2 x 256
    gemm_k<MODE_Q><<<gP, 256>>>(x,      Wq, x_pe, CDIM, CDIM);
    gemm_k<MODE_K><<<gP, 256>>>(source, Wk, s_pe, CDIM, CDIM);
    gemm_k<MODE_V><<<gP, 256>>>(source, Wv, s_pe, CDIM, CDIM);

    kv_kernel<<<dim3(NBATCH * HHEADS, 8), 256>>>();
    queried_kernel<<<NBATCH * (LSEQ / 64), 256>>>();

    gemm_k<MODE_M><<<gP, 256>>>(nullptr, Wm, nullptr, CDIM, CDIM);
    ln1_kernel<<<MROWS, 256>>>(ln1_g, ln1_b);

    dim3 gH(2 * CDIM / 128, MROWS / 128);       // 4 x 256
    gemm_k<MODE_H><<<gH, 256>>>(x, W1, nullptr, 2 * CDIM, 2 * CDIM);
    gemm_k<MODE_O><<<gP, 256>>>(nullptr, W2, nullptr, 2 * CDIM, CDIM);

    ln2_res_kernel<<<MROWS, 256>>>(x, ln2_g, ln2_b, out);
}